// round 9
// baseline (speedup 1.0000x reference)
#include <cuda_runtime.h>
#include <cuda_fp16.h>
#include <cstdint>

#define DINL __device__ __forceinline__

// ===================== problem dims =====================
#define M_TOT 4096
#define N_TOT 4096
#define K_TOT 4096
#define NUM_GROUPS 524288   // (4096*4096)/32

// ===================== GEMM tiling ======================
// CTA 128x256, 8 warps in 2(m) x 4(n), warp tile 64x64, BK=64 (fp16).
// Persistent: grid=148 CTAs, each owns tiles bid, bid+148, ... of 512.
#define BM 128
#define BN 256
#define BK 64
#define NKT (K_TOT / BK)                 // 64 k-tiles
#define NTILES ((M_TOT / BM) * (N_TOT / BN))   // 512
#define GRID 148
#define STAGES 4
#define A_TILE_BYTES (BM * BK * 2)       // 16384
#define B_TILE_BYTES (BN * BK * 2)       // 32768
#define STAGE_BYTES (A_TILE_BYTES + B_TILE_BYTES)    // 49152
#define SMEM_HDR 1024
#define SMEM_TOTAL (SMEM_HDR + STAGES * STAGE_BYTES) // 197632

// 32MB + 32MB static scratch: fragment-major tiled fp16 operands (as b32 pairs)
__device__ uint32_t g_A[8388608];
__device__ uint32_t g_W[8388608];
#define A_TILE_U32 4096   // 16KB tile
#define B_TILE_U32 8192   // 32KB tile
#define PREPX_BLOCKS 16384

// ===================== helpers ==========================
DINL uint32_t smem_u32(const void* p) {
  uint32_t a;
  asm("{ .reg .u64 t; cvta.to.shared.u64 t, %1; cvt.u32.u64 %0, t; }" : "=r"(a) : "l"(p));
  return a;
}
DINL uint32_t pack_half2(float lo, float hi) {  // b32 = {hi:lo} fp16x2
  uint32_t u;
  asm("cvt.rn.f16x2.f32 %0, %1, %2;" : "=r"(u) : "f"(hi), "f"(lo));
  return u;
}

#define MBAR_INIT(a, n) \
  asm volatile("mbarrier.init.shared.b64 [%0], %1;" :: "r"(a), "r"(n) : "memory")
#define MBAR_EXPECT_TX(a, b) \
  asm volatile("mbarrier.arrive.expect_tx.shared.b64 _, [%0], %1;" :: "r"(a), "r"(b) : "memory")
#define MBAR_ARRIVE(a) \
  asm volatile("mbarrier.arrive.shared.b64 _, [%0];" :: "r"(a) : "memory")

DINL void mbar_wait(uint32_t mbar, uint32_t parity) {
  asm volatile(
      "{\n\t.reg .pred P;\n\t"
      "W_%=:\n\t"
      "mbarrier.try_wait.parity.acquire.cta.shared::cta.b64 P, [%0], %1, 0x989680;\n\t"
      "@!P bra.uni W_%=;\n\t}"
      :: "r"(mbar), "r"(parity) : "memory");
}

DINL void bulk_g2s(uint32_t dst, const void* src, uint32_t bytes, uint32_t mbar) {
  asm volatile(
      "cp.async.bulk.shared::cta.global.mbarrier::complete_tx::bytes [%0], [%1], %2, [%3];"
      :: "r"(dst), "l"(src), "r"(bytes), "r"(mbar) : "memory");
}

#define LDS128(r, addr) \
  asm volatile("ld.shared.v4.b32 {%0,%1,%2,%3}, [%4];" \
               : "=r"((r)[0]), "=r"((r)[1]), "=r"((r)[2]), "=r"((r)[3]) : "r"(addr))

DINL void mma_f16(float* d, const uint32_t* a, uint32_t b0, uint32_t b1) {
  asm volatile(
      "mma.sync.aligned.m16n8k16.row.col.f32.f16.f16.f32 "
      "{%0,%1,%2,%3}, {%4,%5,%6,%7}, {%8,%9}, {%0,%1,%2,%3};"
      : "+f"(d[0]), "+f"(d[1]), "+f"(d[2]), "+f"(d[3])
      : "r"(a[0]), "r"(a[1]), "r"(a[2]), "r"(a[3]), "r"(b0), "r"(b1));
}

// ===================== fused prep: x->tiles  +  dequant W->tiles ============
// part 1 (blocks [0, 16384)): x -> g_A fragment-major fp16 tiles.
//   g_A: [mtile(32)][kt(64)] tiles of 16KB = [ks(4)][mfrag(8)][lane(32)][4xb32]
//   m16n8k16 A frag: a0=(r,2c) a1=(r+8,2c) a2=(r,2c+8) a3=(r+8,2c+8), lane=(r&7)*4+c.
// part 2 (blocks [16384, 18432)): 3-bit dequant -> g_W fragment-major fp16 tiles.
//   g_W: [ntile(16)][kt(64)] tiles of 32KB = [ks(4)][pair(16)][lane(32)][4xb32];
//   16B packs two n8 B frags {fE.b0, fE.b1, fO.b0, fO.b1};
//   B frag: b0=(k=2(lane&3)+{0,1}, n=lane>>2), b1 same with k+8.
__global__ void prep_kernel(const float* __restrict__ x,
                            const int4* __restrict__ q3,
                            const float* __restrict__ norm) {
  if (blockIdx.x < PREPX_BLOCKS) {
    const int idx = blockIdx.x * blockDim.x + threadIdx.x;  // float4 id
    const int m = idx >> 10;          // 1024 float4 per row of 4096
    const int c4 = idx & 1023;        // k0 = c4*4
    const int kt = c4 >> 4;
    const int ks = (c4 >> 2) & 3;
    const int kk = (c4 & 3) * 4;      // k within K=16 step: {0,4,8,12}
    float4 v = reinterpret_cast<const float4*>(x)[idx];
    const uint32_t h01 = pack_half2(v.x, v.y);
    const uint32_t h23 = pack_half2(v.z, v.w);
    const int r16 = m & 15;
    const int mfrag = (m >> 4) & 7;
    const int reg = (r16 >> 3) + ((kk >> 3) << 1);     // a0..a3 slot
    const int lane0 = (r16 & 7) * 4 + ((kk & 7) >> 1);
    uint32_t* tile = g_A + (size_t)((m >> 7) * NKT + kt) * A_TILE_U32;
    const int base = ((ks * 8 + mfrag) * 32) * 4;
    tile[base + lane0 * 4 + reg] = h01;
    tile[base + (lane0 + 1) * 4 + reg] = h23;
  } else {
    const int g = (blockIdx.x - PREPX_BLOCKS) * blockDim.x + threadIdx.x;  // group id
    const int o = g >> 7;        // output feature (n)
    const int kg = g & 127;      // 32-wide k-group
    const float sc = norm[g];
    const float a = sc * (2.0f / 7.0f);
    const int4 pa = q3[g * 3 + 0];
    const int4 pb = q3[g * 3 + 1];
    const int4 pc = q3[g * 3 + 2];
    const unsigned b[12] = {(unsigned)pa.x, (unsigned)pa.y, (unsigned)pa.z, (unsigned)pa.w,
                            (unsigned)pb.x, (unsigned)pb.y, (unsigned)pb.z, (unsigned)pb.w,
                            (unsigned)pc.x, (unsigned)pc.y, (unsigned)pc.z, (unsigned)pc.w};
    const int nr = o & 255;
    const int pair = nr >> 4;
    const int nsub = (nr >> 3) & 1;    // which n8 frag in the 16B pack
    const int ncol = nr & 7;           // lane>>2
    uint32_t* tile = g_W + (size_t)((o >> 8) * NKT + (kg >> 1)) * B_TILE_U32;
#pragma unroll
    for (int t = 0; t < 4; t++) {   // triplet: 8 values, k = kg*32 + t*8 ..
      const unsigned b0 = b[3 * t + 0], b1 = b[3 * t + 1], b2 = b[3 * t + 2];
      unsigned v[8];
      v[0] = b0 & 7u;
      v[1] = (b0 >> 3) & 7u;
      v[2] = ((b0 >> 6) & 3u) | ((b1 & 1u) << 2);
      v[3] = (b1 >> 1) & 7u;
      v[4] = (b1 >> 4) & 7u;
      v[5] = ((b1 >> 7) & 1u) | ((b2 & 3u) << 1);
      v[6] = (b2 >> 2) & 7u;
      v[7] = (b2 >> 5) & 7u;
      const int ks = (kg & 1) * 2 + (t >> 1);
      const int reg = nsub * 2 + (t & 1);            // b0 vs b1 half, even/odd frag
      const int base = ((ks * 16 + pair) * 32) * 4;
#pragma unroll
      for (int i = 0; i < 8; i += 2) {
        const float w0 = fmaf((float)v[i], a, -sc);
        const float w1 = fmaf((float)v[i + 1], a, -sc);
        const int lane = ncol * 4 + (i >> 1);
        tile[base + lane * 4 + reg] = pack_half2(w0, w1);
      }
    }
  }
}

// ===================== main GEMM (persistent) =====================
// Global k-tile stream g in [0, ntiles*64): tile = bid + GRID*(g>>6), kt = g&63.
// Pipeline (4 stages) runs continuously across tile boundaries, so the next
// tile's loads overlap the current tile's epilogue.
DINL void produce_stage(uint32_t sb, int bid, int G) {
  const int t = bid + GRID * (G >> 6);
  const int kt = G & 63;
  const int s = G & (STAGES - 1);
  const uint32_t full = sb + 8 * s;
  const char* srcA = (const char*)g_A + (size_t)((t >> 4) * NKT + kt) * A_TILE_BYTES;
  const char* srcB = (const char*)g_W + (size_t)((t & 15) * NKT + kt) * B_TILE_BYTES;
  MBAR_EXPECT_TX(full, (uint32_t)STAGE_BYTES);
  const uint32_t dst = sb + SMEM_HDR + s * STAGE_BYTES;
  bulk_g2s(dst, srcA, A_TILE_BYTES, full);
  bulk_g2s(dst + A_TILE_BYTES, srcB, B_TILE_BYTES, full);
}

__global__ void __launch_bounds__(256, 1)
gemm_kernel(const float* __restrict__ bias, float* __restrict__ out) {
  extern __shared__ __align__(1024) char smem[];
  const uint32_t sb = smem_u32(smem);
  const int tid = threadIdx.x;
  const int wid = tid >> 5;
  const int lane = tid & 31;
  const int wr = wid >> 2;   // 0..1 (m)
  const int wc = wid & 3;    // 0..3 (n)
  const int bid = blockIdx.x;

  const uint32_t mb_full = sb;
  const uint32_t mb_empty = sb + 8 * STAGES;

  int ntiles = 0;
  for (int t = bid; t < NTILES; t += GRID) ntiles++;
  const int totKt = ntiles * NKT;

  if (tid == 0) {
    for (int i = 0; i < STAGES; i++) {
      MBAR_INIT(mb_full + 8 * i, 1);
      MBAR_INIT(mb_empty + 8 * i, 256);
    }
    asm volatile("fence.proxy.async.shared::cta;" ::: "memory");
  }
  __syncthreads();

  if (tid == 0) {
#pragma unroll
    for (int G = 0; G < STAGES; G++)
      if (G < totKt) produce_stage(mb_full, bid, G);
  }

  const uint32_t a_lane_off = (wr * 4) * 512 + lane * 16;   // mfrag stride 512B
  const uint32_t b_lane_off = (wc * 4) * 512 + lane * 16;   // pair stride 512B

  int g = 0;
  for (int ti = 0; ti < ntiles; ti++) {
    const int t = bid + GRID * ti;
    const int mt = t >> 4;
    const int nt = t & 15;

    float acc[4][8][4];
#pragma unroll
    for (int i = 0; i < 4; i++)
#pragma unroll
      for (int j = 0; j < 8; j++)
#pragma unroll
        for (int c = 0; c < 4; c++) acc[i][j][c] = 0.0f;

    for (int kt = 0; kt < NKT; kt++, g++) {
      const int s = g & (STAGES - 1);
      const uint32_t ph = (g >> 2) & 1;
      mbar_wait(mb_full + 8 * s, ph);
      const uint32_t aB = sb + SMEM_HDR + s * STAGE_BYTES;
      const uint32_t bB = aB + A_TILE_BYTES;

      uint32_t af[2][4][4], bf[2][4][4];
      // prefetch ks=0
#pragma unroll
      for (int mf = 0; mf < 4; mf++) LDS128(af[0][mf], aB + a_lane_off + mf * 512);
#pragma unroll
      for (int p = 0; p < 4; p++) LDS128(bf[0][p], bB + b_lane_off + p * 512);

#pragma unroll
      for (int ks = 0; ks < 4; ks++) {
        const int cur = ks & 1, nxt = cur ^ 1;
        if (ks < 3) {
          const uint32_t a_addr = aB + (ks + 1) * (8 * 512) + a_lane_off;
          const uint32_t b_addr = bB + (ks + 1) * (16 * 512) + b_lane_off;
#pragma unroll
          for (int mf = 0; mf < 4; mf++) LDS128(af[nxt][mf], a_addr + mf * 512);
#pragma unroll
          for (int p = 0; p < 4; p++) LDS128(bf[nxt][p], b_addr + p * 512);
        }
#pragma unroll
        for (int mf = 0; mf < 4; mf++)
#pragma unroll
          for (int p = 0; p < 4; p++) {
            mma_f16(acc[mf][2 * p + 0], af[cur][mf], bf[cur][p][0], bf[cur][p][1]);
            mma_f16(acc[mf][2 * p + 1], af[cur][mf], bf[cur][p][2], bf[cur][p][3]);
          }
      }
      MBAR_ARRIVE(mb_empty + 8 * s);
      if (tid == 0) {
        const int G = g + STAGES;
        if (G < totKt) {
          mbar_wait(mb_empty + 8 * s, ph);  // all 256 done with this stage's prior use
          produce_stage(mb_full, bid, G);
        }
      }
    }

    // ---------------- epilogue: acc + bias -> out (overlaps next-tile loads) --
    const int m_base = mt * BM + wr * 64 + (lane >> 2);
    const int n_base = nt * BN + wc * 64 + (lane & 3) * 2;
#pragma unroll
    for (int mf = 0; mf < 4; mf++) {
      const int m0 = m_base + mf * 16;
#pragma unroll
      for (int nf = 0; nf < 8; nf++) {
        const int n = n_base + nf * 8;
        const float2 bv = *reinterpret_cast<const float2*>(bias + n);
        float2 v0, v1;
        v0.x = acc[mf][nf][0] + bv.x;
        v0.y = acc[mf][nf][1] + bv.y;
        v1.x = acc[mf][nf][2] + bv.x;
        v1.y = acc[mf][nf][3] + bv.y;
        *reinterpret_cast<float2*>(out + (size_t)m0 * N_TOT + n) = v0;
        *reinterpret_cast<float2*>(out + (size_t)(m0 + 8) * N_TOT + n) = v1;
      }
    }
  }
}

// ===================== launch =====================
extern "C" void kernel_launch(void* const* d_in, const int* in_sizes, int n_in,
                              void* d_out, int out_size) {
  const float* x    = (const float*)d_in[0];   // [2,2048,4096] f32
  const int4*  q3   = (const int4*)d_in[1];    // [NUM_GROUPS*12] int32 byte values
  const float* norm = (const float*)d_in[2];   // [NUM_GROUPS] f32
  const float* bias = (const float*)d_in[3];   // [4096] f32
  float* out = (float*)d_out;                  // [2,2048,4096] f32

  prep_kernel<<<PREPX_BLOCKS + NUM_GROUPS / 256, 256>>>(x, q3, norm);

  cudaFuncSetAttribute(gemm_kernel, cudaFuncAttributeMaxDynamicSharedMemorySize, SMEM_TOTAL);
  gemm_kernel<<<GRID, 256, SMEM_TOTAL>>>(bias, out);
}

// round 10
// speedup vs baseline: 1.1326x; 1.1326x over previous
#include <cuda_runtime.h>
#include <cuda_fp16.h>
#include <cstdint>

#define DINL __device__ __forceinline__

// ===================== problem dims =====================
#define M_TOT 4096
#define N_TOT 4096
#define K_TOT 4096
#define NUM_GROUPS 524288   // (4096*4096)/32

// ===================== GEMM tiling ======================
// CTA 128x128, 8 compute warps in 2(m) x 4(n), warp tile 64x32, BK=64 (fp16).
// +1 producer warp (288 threads). Persistent grid=148; 1024 tiles -> 6.92 mean,
// 7 max tiles per CTA (1% imbalance vs 13% at BN=256).
#define BM 128
#define BN 128
#define BK 64
#define NKT (K_TOT / BK)                 // 64 k-tiles
#define NTILES ((M_TOT / BM) * (N_TOT / BN))   // 1024
#define GRID 148
#define STAGES 6
#define A_TILE_BYTES (BM * BK * 2)       // 16384
#define B_TILE_BYTES (BN * BK * 2)       // 16384
#define STAGE_BYTES (A_TILE_BYTES + B_TILE_BYTES)    // 32768
#define SMEM_HDR 1024
#define SMEM_TOTAL (SMEM_HDR + STAGES * STAGE_BYTES) // 197632

// 32MB + 32MB static scratch: fragment-major tiled fp16 operands (as b32 pairs)
__device__ uint32_t g_A[8388608];
__device__ uint32_t g_W[8388608];
#define A_TILE_U32 4096   // 16KB tile
#define B_TILE_U32 4096   // 16KB tile

// ===================== helpers ==========================
DINL uint32_t smem_u32(const void* p) {
  uint32_t a;
  asm("{ .reg .u64 t; cvta.to.shared.u64 t, %1; cvt.u32.u64 %0, t; }" : "=r"(a) : "l"(p));
  return a;
}
DINL uint32_t pack_half2(float lo, float hi) {  // b32 = {hi:lo} fp16x2
  uint32_t u;
  asm("cvt.rn.f16x2.f32 %0, %1, %2;" : "=r"(u) : "f"(hi), "f"(lo));
  return u;
}
DINL uint32_t elect_one() {
  uint32_t p;
  asm volatile("{ .reg .pred p; elect.sync _|p, 0xFFFFFFFF; selp.b32 %0, 1, 0, p; }" : "=r"(p));
  return p;
}

#define MBAR_INIT(a, n) \
  asm volatile("mbarrier.init.shared.b64 [%0], %1;" :: "r"(a), "r"(n) : "memory")
#define MBAR_EXPECT_TX(a, b) \
  asm volatile("mbarrier.arrive.expect_tx.shared.b64 _, [%0], %1;" :: "r"(a), "r"(b) : "memory")
#define MBAR_ARRIVE(a) \
  asm volatile("mbarrier.arrive.shared.b64 _, [%0];" :: "r"(a) : "memory")

DINL void mbar_wait(uint32_t mbar, uint32_t parity) {
  asm volatile(
      "{\n\t.reg .pred P;\n\t"
      "W_%=:\n\t"
      "mbarrier.try_wait.parity.acquire.cta.shared::cta.b64 P, [%0], %1, 0x989680;\n\t"
      "@!P bra.uni W_%=;\n\t}"
      :: "r"(mbar), "r"(parity) : "memory");
}

DINL void bulk_g2s(uint32_t dst, const void* src, uint32_t bytes, uint32_t mbar) {
  asm volatile(
      "cp.async.bulk.shared::cta.global.mbarrier::complete_tx::bytes [%0], [%1], %2, [%3];"
      :: "r"(dst), "l"(src), "r"(bytes), "r"(mbar) : "memory");
}

#define LDS128(r, addr) \
  asm volatile("ld.shared.v4.b32 {%0,%1,%2,%3}, [%4];" \
               : "=r"((r)[0]), "=r"((r)[1]), "=r"((r)[2]), "=r"((r)[3]) : "r"(addr))

DINL void mma_f16(float* d, const uint32_t* a, uint32_t b0, uint32_t b1) {
  asm volatile(
      "mma.sync.aligned.m16n8k16.row.col.f32.f16.f16.f32 "
      "{%0,%1,%2,%3}, {%4,%5,%6,%7}, {%8,%9}, {%0,%1,%2,%3};"
      : "+f"(d[0]), "+f"(d[1]), "+f"(d[2]), "+f"(d[3])
      : "r"(a[0]), "r"(a[1]), "r"(a[2]), "r"(a[3]), "r"(b0), "r"(b1));
}

// ===================== prep: x -> fragment-major tiled fp16 =====================
// g_A: [mtile(32)][kt(64)] tiles of 16KB = [ks(4)][mfrag(8)][lane(32)][4xb32].
// m16n8k16 A frag: a0=(r,2c) a1=(r+8,2c) a2=(r,2c+8) a3=(r+8,2c+8), lane=(r&7)*4+c.
__global__ void prep_x_kernel(const float* __restrict__ x) {
  const int idx = blockIdx.x * blockDim.x + threadIdx.x;  // float4 id
  const int m = idx >> 10;          // 1024 float4 per row of 4096
  const int c4 = idx & 1023;        // k0 = c4*4
  const int kt = c4 >> 4;
  const int ks = (c4 >> 2) & 3;
  const int kk = (c4 & 3) * 4;      // k within K=16 step: {0,4,8,12}
  float4 v = reinterpret_cast<const float4*>(x)[idx];
  const uint32_t h01 = pack_half2(v.x, v.y);
  const uint32_t h23 = pack_half2(v.z, v.w);
  const int r16 = m & 15;
  const int mfrag = (m >> 4) & 7;
  const int reg = (r16 >> 3) + ((kk >> 3) << 1);     // a0..a3 slot
  const int lane0 = (r16 & 7) * 4 + ((kk & 7) >> 1);
  uint32_t* tile = g_A + (size_t)((m >> 7) * NKT + kt) * A_TILE_U32;
  const int base = ((ks * 8 + mfrag) * 32) * 4;
  tile[base + lane0 * 4 + reg] = h01;
  tile[base + (lane0 + 1) * 4 + reg] = h23;
}

// ===================== prep: dequant W -> fragment-major tiled fp16 =====================
// g_W: [ntile(32)][kt(64)] tiles of 16KB = [ks(4)][pair(8)][lane(32)][4xb32];
// 16B packs two n8 B frags {fE.b0, fE.b1, fO.b0, fO.b1};
// B frag: b0=(k=2(lane&3)+{0,1}, n=lane>>2), b1 same with k+8.
__global__ void dequant_kernel(const int4* __restrict__ q3, const float* __restrict__ norm) {
  const int g = blockIdx.x * blockDim.x + threadIdx.x;  // group id
  const int o = g >> 7;        // output feature (n)
  const int kg = g & 127;      // 32-wide k-group
  const float sc = norm[g];
  const float a = sc * (2.0f / 7.0f);
  const int4 pa = q3[g * 3 + 0];
  const int4 pb = q3[g * 3 + 1];
  const int4 pc = q3[g * 3 + 2];
  const unsigned b[12] = {(unsigned)pa.x, (unsigned)pa.y, (unsigned)pa.z, (unsigned)pa.w,
                          (unsigned)pb.x, (unsigned)pb.y, (unsigned)pb.z, (unsigned)pb.w,
                          (unsigned)pc.x, (unsigned)pc.y, (unsigned)pc.z, (unsigned)pc.w};
  const int nr = o & 127;
  const int pair = nr >> 4;          // 0..7
  const int nsub = (nr >> 3) & 1;    // which n8 frag in the 16B pack
  const int ncol = nr & 7;           // lane>>2
  uint32_t* tile = g_W + (size_t)((o >> 7) * NKT + (kg >> 1)) * B_TILE_U32;
#pragma unroll
  for (int t = 0; t < 4; t++) {   // triplet: 8 values, k = kg*32 + t*8 ..
    const unsigned b0 = b[3 * t + 0], b1 = b[3 * t + 1], b2 = b[3 * t + 2];
    unsigned v[8];
    v[0] = b0 & 7u;
    v[1] = (b0 >> 3) & 7u;
    v[2] = ((b0 >> 6) & 3u) | ((b1 & 1u) << 2);
    v[3] = (b1 >> 1) & 7u;
    v[4] = (b1 >> 4) & 7u;
    v[5] = ((b1 >> 7) & 1u) | ((b2 & 3u) << 1);
    v[6] = (b2 >> 2) & 7u;
    v[7] = (b2 >> 5) & 7u;
    const int ks = (kg & 1) * 2 + (t >> 1);
    const int reg = nsub * 2 + (t & 1);            // b0 vs b1 half, even/odd frag
    const int base = ((ks * 8 + pair) * 32) * 4;
#pragma unroll
    for (int i = 0; i < 8; i += 2) {
      const float w0 = fmaf((float)v[i], a, -sc);
      const float w1 = fmaf((float)v[i + 1], a, -sc);
      const int lane = ncol * 4 + (i >> 1);
      tile[base + lane * 4 + reg] = pack_half2(w0, w1);
    }
  }
}

// ===================== main GEMM (persistent, producer warp) =====================
// Global k-tile stream G in [0, ntiles*64): tile = bid + GRID*(G>>6), kt = G&63.
DINL void produce_stage(uint32_t mb_full, uint32_t sb, int bid, int G, int s) {
  const int t = bid + GRID * (G >> 6);
  const int kt = G & 63;
  const uint32_t full = mb_full + 8 * s;
  const char* srcA = (const char*)g_A + (size_t)((t >> 5) * NKT + kt) * A_TILE_BYTES;
  const char* srcB = (const char*)g_W + (size_t)((t & 31) * NKT + kt) * B_TILE_BYTES;
  MBAR_EXPECT_TX(full, (uint32_t)STAGE_BYTES);
  const uint32_t dst = sb + SMEM_HDR + s * STAGE_BYTES;
  bulk_g2s(dst, srcA, A_TILE_BYTES, full);
  bulk_g2s(dst + A_TILE_BYTES, srcB, B_TILE_BYTES, full);
}

__global__ void __launch_bounds__(288, 1)
gemm_kernel(const float* __restrict__ bias, float* __restrict__ out) {
  extern __shared__ __align__(1024) char smem[];
  const uint32_t sb = smem_u32(smem);
  const int tid = threadIdx.x;
  const int wid = tid >> 5;
  const int lane = tid & 31;
  const int bid = blockIdx.x;

  const uint32_t mb_full = sb;                    // STAGES mbarriers, count 1
  const uint32_t mb_empty = sb + 8 * STAGES;      // STAGES mbarriers, count 8

  int ntiles = 0;
  for (int t = bid; t < NTILES; t += GRID) ntiles++;
  const int totKt = ntiles * NKT;

  if (tid == 0) {
    for (int i = 0; i < STAGES; i++) {
      MBAR_INIT(mb_full + 8 * i, 1);
      MBAR_INIT(mb_empty + 8 * i, 8);
    }
    asm volatile("fence.proxy.async.shared::cta;" ::: "memory");
  }
  __syncthreads();

  if (wid == 8) {
    // ---------------- dedicated producer warp ----------------
    if (elect_one()) {
      int s = 0;
      uint32_t pe = 0;
      for (int G = 0; G < totKt; G++) {
        if (G >= STAGES) mbar_wait(mb_empty + 8 * s, pe);
        produce_stage(mb_full, sb, bid, G, s);
        if (++s == STAGES) { s = 0; if (G > STAGES) pe ^= 1; }
      }
    }
    return;
  }

  // ---------------- compute warps 0-7: 2(m) x 4(n), warp tile 64x32 ---------
  const int wr = wid >> 2;   // 0..1 (m)
  const int wc = wid & 3;    // 0..3 (n)
  const uint32_t a_lane_off = (wr * 4) * 512 + lane * 16;   // mfrag stride 512B
  const uint32_t b_lane_off = (wc * 2) * 512 + lane * 16;   // pair stride 512B

  int s = 0;
  uint32_t pf = 0;
  for (int ti = 0; ti < ntiles; ti++) {
    const int t = bid + GRID * ti;
    const int mt = t >> 5;
    const int nt = t & 31;

    float acc[4][4][4];
#pragma unroll
    for (int i = 0; i < 4; i++)
#pragma unroll
      for (int j = 0; j < 4; j++)
#pragma unroll
        for (int c = 0; c < 4; c++) acc[i][j][c] = 0.0f;

    for (int kt = 0; kt < NKT; kt++) {
      mbar_wait(mb_full + 8 * s, pf);
      const uint32_t aB = sb + SMEM_HDR + s * STAGE_BYTES;
      const uint32_t bB = aB + A_TILE_BYTES;

      uint32_t af[2][4][4], bf[2][2][4];
      // prefetch ks=0
#pragma unroll
      for (int mf = 0; mf < 4; mf++) LDS128(af[0][mf], aB + a_lane_off + mf * 512);
#pragma unroll
      for (int p = 0; p < 2; p++) LDS128(bf[0][p], bB + b_lane_off + p * 512);

#pragma unroll
      for (int ks = 0; ks < 4; ks++) {
        const int cur = ks & 1, nxt = cur ^ 1;
        if (ks < 3) {
          const uint32_t a_addr = aB + (ks + 1) * (8 * 512) + a_lane_off;
          const uint32_t b_addr = bB + (ks + 1) * (8 * 512) + b_lane_off;
#pragma unroll
          for (int mf = 0; mf < 4; mf++) LDS128(af[nxt][mf], a_addr + mf * 512);
#pragma unroll
          for (int p = 0; p < 2; p++) LDS128(bf[nxt][p], b_addr + p * 512);
        }
#pragma unroll
        for (int mf = 0; mf < 4; mf++)
#pragma unroll
          for (int p = 0; p < 2; p++) {
            mma_f16(acc[mf][2 * p + 0], af[cur][mf], bf[cur][p][0], bf[cur][p][1]);
            mma_f16(acc[mf][2 * p + 1], af[cur][mf], bf[cur][p][2], bf[cur][p][3]);
          }
      }
      if (lane == 0) MBAR_ARRIVE(mb_empty + 8 * s);
      if (++s == STAGES) { s = 0; pf ^= 1; }
    }

    // ---------------- epilogue: acc + bias -> out (overlaps producer) -------
    const int m_base = mt * BM + wr * 64 + (lane >> 2);
    const int n_base = nt * BN + wc * 32 + (lane & 3) * 2;
#pragma unroll
    for (int mf = 0; mf < 4; mf++) {
      const int m0 = m_base + mf * 16;
#pragma unroll
      for (int nf = 0; nf < 4; nf++) {
        const int n = n_base + nf * 8;
        const float2 bv = *reinterpret_cast<const float2*>(bias + n);
        float2 v0, v1;
        v0.x = acc[mf][nf][0] + bv.x;
        v0.y = acc[mf][nf][1] + bv.y;
        v1.x = acc[mf][nf][2] + bv.x;
        v1.y = acc[mf][nf][3] + bv.y;
        *reinterpret_cast<float2*>(out + (size_t)m0 * N_TOT + n) = v0;
        *reinterpret_cast<float2*>(out + (size_t)(m0 + 8) * N_TOT + n) = v1;
      }
    }
  }
}

// ===================== launch =====================
extern "C" void kernel_launch(void* const* d_in, const int* in_sizes, int n_in,
                              void* d_out, int out_size) {
  const float* x    = (const float*)d_in[0];   // [2,2048,4096] f32
  const int4*  q3   = (const int4*)d_in[1];    // [NUM_GROUPS*12] int32 byte values
  const float* norm = (const float*)d_in[2];   // [NUM_GROUPS] f32
  const float* bias = (const float*)d_in[3];   // [4096] f32
  float* out = (float*)d_out;                  // [2,2048,4096] f32

  prep_x_kernel<<<(M_TOT * K_TOT / 4) / 256, 256>>>(x);
  dequant_kernel<<<NUM_GROUPS / 256, 256>>>(q3, norm);

  cudaFuncSetAttribute(gemm_kernel, cudaFuncAttributeMaxDynamicSharedMemorySize, SMEM_TOTAL);
  gemm_kernel<<<GRID, 288, SMEM_TOTAL>>>(bias, out);
}

// round 11
// speedup vs baseline: 1.1706x; 1.0336x over previous
#include <cuda_runtime.h>
#include <cuda_fp16.h>
#include <cstdint>

#define DINL __device__ __forceinline__

// ===================== problem dims =====================
#define M_TOT 4096
#define N_TOT 4096
#define K_TOT 4096
#define NUM_GROUPS 524288   // (4096*4096)/32

// ===================== GEMM tiling ======================
// CTA 128x128, 8 compute warps in 2(m) x 4(n), warp tile 64x32.
// Stage = 2 consecutive k-tiles (BK_STAGE=128): A 32KB + B 32KB. 3 stages.
// +1 producer warp (288 threads). Persistent grid=148 over 1024 tiles.
#define BM 128
#define BN 128
#define BK 64                            // per k-tile (layout unit)
#define NKT (K_TOT / BK)                 // 64 k-tiles
#define UNITS_PER_TILE (NKT / 2)         // 32 stage-units per tile
#define NTILES ((M_TOT / BM) * (N_TOT / BN))   // 1024
#define GRID 148
#define STAGES 3
#define A_TILE_BYTES (BM * BK * 2)       // 16384
#define B_TILE_BYTES (BN * BK * 2)       // 16384
#define A_STAGE_BYTES (2 * A_TILE_BYTES) // 32768
#define B_STAGE_BYTES (2 * B_TILE_BYTES) // 32768
#define STAGE_BYTES (A_STAGE_BYTES + B_STAGE_BYTES)  // 65536
#define SMEM_HDR 1024
#define SMEM_TOTAL (SMEM_HDR + STAGES * STAGE_BYTES) // 197632

// 32MB + 32MB static scratch: fragment-major tiled fp16 operands (as b32 pairs)
__device__ uint32_t g_A[8388608];
__device__ uint32_t g_W[8388608];
#define A_TILE_U32 4096   // 16KB tile
#define B_TILE_U32 4096   // 16KB tile
#define PREPX_BLOCKS 16384
#define PREP_GRID 18432   // 16384 prep_x + 2048 dequant, interleaved by bid%9

// ===================== helpers ==========================
DINL uint32_t smem_u32(const void* p) {
  uint32_t a;
  asm("{ .reg .u64 t; cvta.to.shared.u64 t, %1; cvt.u32.u64 %0, t; }" : "=r"(a) : "l"(p));
  return a;
}
DINL uint32_t pack_half2(float lo, float hi) {  // b32 = {hi:lo} fp16x2
  uint32_t u;
  asm("cvt.rn.f16x2.f32 %0, %1, %2;" : "=r"(u) : "f"(hi), "f"(lo));
  return u;
}
DINL uint32_t elect_one() {
  uint32_t p;
  asm volatile("{ .reg .pred p; elect.sync _|p, 0xFFFFFFFF; selp.b32 %0, 1, 0, p; }" : "=r"(p));
  return p;
}

#define MBAR_INIT(a, n) \
  asm volatile("mbarrier.init.shared.b64 [%0], %1;" :: "r"(a), "r"(n) : "memory")
#define MBAR_EXPECT_TX(a, b) \
  asm volatile("mbarrier.arrive.expect_tx.shared.b64 _, [%0], %1;" :: "r"(a), "r"(b) : "memory")
#define MBAR_ARRIVE(a) \
  asm volatile("mbarrier.arrive.shared.b64 _, [%0];" :: "r"(a) : "memory")

DINL void mbar_wait(uint32_t mbar, uint32_t parity) {
  asm volatile(
      "{\n\t.reg .pred P;\n\t"
      "W_%=:\n\t"
      "mbarrier.try_wait.parity.acquire.cta.shared::cta.b64 P, [%0], %1, 0x989680;\n\t"
      "@!P bra.uni W_%=;\n\t}"
      :: "r"(mbar), "r"(parity) : "memory");
}

DINL void bulk_g2s(uint32_t dst, const void* src, uint32_t bytes, uint32_t mbar) {
  asm volatile(
      "cp.async.bulk.shared::cta.global.mbarrier::complete_tx::bytes [%0], [%1], %2, [%3];"
      :: "r"(dst), "l"(src), "r"(bytes), "r"(mbar) : "memory");
}

#define LDS128(r, addr) \
  asm volatile("ld.shared.v4.b32 {%0,%1,%2,%3}, [%4];" \
               : "=r"((r)[0]), "=r"((r)[1]), "=r"((r)[2]), "=r"((r)[3]) : "r"(addr))

DINL void mma_f16(float* d, const uint32_t* a, uint32_t b0, uint32_t b1) {
  asm volatile(
      "mma.sync.aligned.m16n8k16.row.col.f32.f16.f16.f32 "
      "{%0,%1,%2,%3}, {%4,%5,%6,%7}, {%8,%9}, {%0,%1,%2,%3};"
      : "+f"(d[0]), "+f"(d[1]), "+f"(d[2]), "+f"(d[3])
      : "r"(a[0]), "r"(a[1]), "r"(a[2]), "r"(a[3]), "r"(b0), "r"(b1));
}

// ===================== fused prep (roles interleaved by bid%9) ==============
// prep_x: x -> g_A [mtile(32)][kt(64)] 16KB tiles = [ks(4)][mfrag(8)][lane(32)][4xb32]
//   m16n8k16 A frag: a0=(r,2c) a1=(r+8,2c) a2=(r,2c+8) a3=(r+8,2c+8), lane=(r&7)*4+c.
// dequant: 3-bit -> g_W [ntile(32)][kt(64)] 16KB tiles = [ks(4)][pair(8)][lane(32)][4xb32]
//   16B packs two n8 B frags {fE.b0, fE.b1, fO.b0, fO.b1};
//   B frag: b0=(k=2(lane&3)+{0,1}, n=lane>>2), b1 same with k+8.
__global__ void prep_kernel(const float* __restrict__ x,
                            const int4* __restrict__ q3,
                            const float* __restrict__ norm) {
  const int r = blockIdx.x % 9;
  const int q = blockIdx.x / 9;
  if (r < 8) {
    const int idx = (q * 8 + r) * blockDim.x + threadIdx.x;  // float4 id
    const int m = idx >> 10;          // 1024 float4 per row of 4096
    const int c4 = idx & 1023;        // k0 = c4*4
    const int kt = c4 >> 4;
    const int ks = (c4 >> 2) & 3;
    const int kk = (c4 & 3) * 4;      // k within K=16 step: {0,4,8,12}
    float4 v = reinterpret_cast<const float4*>(x)[idx];
    const uint32_t h01 = pack_half2(v.x, v.y);
    const uint32_t h23 = pack_half2(v.z, v.w);
    const int r16 = m & 15;
    const int mfrag = (m >> 4) & 7;
    const int reg = (r16 >> 3) + ((kk >> 3) << 1);     // a0..a3 slot
    const int lane0 = (r16 & 7) * 4 + ((kk & 7) >> 1);
    uint32_t* tile = g_A + (size_t)((m >> 7) * NKT + kt) * A_TILE_U32;
    const int base = ((ks * 8 + mfrag) * 32) * 4;
    tile[base + lane0 * 4 + reg] = h01;
    tile[base + (lane0 + 1) * 4 + reg] = h23;
  } else {
    const int g = q * blockDim.x + threadIdx.x;  // group id
    const int o = g >> 7;        // output feature (n)
    const int kg = g & 127;      // 32-wide k-group
    const float sc = norm[g];
    const float a = sc * (2.0f / 7.0f);
    const int4 pa = q3[g * 3 + 0];
    const int4 pb = q3[g * 3 + 1];
    const int4 pc = q3[g * 3 + 2];
    const unsigned b[12] = {(unsigned)pa.x, (unsigned)pa.y, (unsigned)pa.z, (unsigned)pa.w,
                            (unsigned)pb.x, (unsigned)pb.y, (unsigned)pb.z, (unsigned)pb.w,
                            (unsigned)pc.x, (unsigned)pc.y, (unsigned)pc.z, (unsigned)pc.w};
    const int nr = o & 127;
    const int pair = nr >> 4;          // 0..7
    const int nsub = (nr >> 3) & 1;    // which n8 frag in the 16B pack
    const int ncol = nr & 7;           // lane>>2
    uint32_t* tile = g_W + (size_t)((o >> 7) * NKT + (kg >> 1)) * B_TILE_U32;
#pragma unroll
    for (int t = 0; t < 4; t++) {   // triplet: 8 values, k = kg*32 + t*8 ..
      const unsigned b0 = b[3 * t + 0], b1 = b[3 * t + 1], b2 = b[3 * t + 2];
      unsigned v[8];
      v[0] = b0 & 7u;
      v[1] = (b0 >> 3) & 7u;
      v[2] = ((b0 >> 6) & 3u) | ((b1 & 1u) << 2);
      v[3] = (b1 >> 1) & 7u;
      v[4] = (b1 >> 4) & 7u;
      v[5] = ((b1 >> 7) & 1u) | ((b2 & 3u) << 1);
      v[6] = (b2 >> 2) & 7u;
      v[7] = (b2 >> 5) & 7u;
      const int ks = (kg & 1) * 2 + (t >> 1);
      const int reg = nsub * 2 + (t & 1);            // b0 vs b1 half, even/odd frag
      const int base = ((ks * 8 + pair) * 32) * 4;
#pragma unroll
      for (int i = 0; i < 8; i += 2) {
        const float w0 = fmaf((float)v[i], a, -sc);
        const float w1 = fmaf((float)v[i + 1], a, -sc);
        const int lane = ncol * 4 + (i >> 1);
        tile[base + lane * 4 + reg] = pack_half2(w0, w1);
      }
    }
  }
}

// ===================== main GEMM (persistent, producer warp) =====================
// Stage-unit stream u in [0, ntiles*32): tile = bid + GRID*(u>>5), kt-pair = u&31.
// Each stage holds 2 consecutive k-tiles (contiguous in g_A/g_W -> single bulk).
DINL void produce_stage(uint32_t mb_full, uint32_t sb, int bid, int u, int s) {
  const int t = bid + GRID * (u >> 5);
  const int kt2 = u & 31;
  const uint32_t full = mb_full + 8 * s;
  const char* srcA = (const char*)g_A + (size_t)((t >> 5) * NKT + kt2 * 2) * A_TILE_BYTES;
  const char* srcB = (const char*)g_W + (size_t)((t & 31) * NKT + kt2 * 2) * B_TILE_BYTES;
  MBAR_EXPECT_TX(full, (uint32_t)STAGE_BYTES);
  const uint32_t dst = sb + SMEM_HDR + s * STAGE_BYTES;
  bulk_g2s(dst, srcA, A_STAGE_BYTES, full);
  bulk_g2s(dst + A_STAGE_BYTES, srcB, B_STAGE_BYTES, full);
}

__global__ void __launch_bounds__(288, 1)
gemm_kernel(const float* __restrict__ bias, float* __restrict__ out) {
  extern __shared__ __align__(1024) char smem[];
  const uint32_t sb = smem_u32(smem);
  const int tid = threadIdx.x;
  const int wid = tid >> 5;
  const int lane = tid & 31;
  const int bid = blockIdx.x;

  const uint32_t mb_full = sb;                    // STAGES mbarriers, count 1
  const uint32_t mb_empty = sb + 8 * STAGES;      // STAGES mbarriers, count 8

  int ntiles = 0;
  for (int t = bid; t < NTILES; t += GRID) ntiles++;
  const int totUnits = ntiles * UNITS_PER_TILE;

  if (tid == 0) {
    for (int i = 0; i < STAGES; i++) {
      MBAR_INIT(mb_full + 8 * i, 1);
      MBAR_INIT(mb_empty + 8 * i, 8);
    }
    asm volatile("fence.proxy.async.shared::cta;" ::: "memory");
  }
  __syncthreads();

  if (wid == 8) {
    // ---------------- dedicated producer warp ----------------
    if (elect_one()) {
      int s = 0, cyc = 0;
      for (int u = 0; u < totUnits; u++) {
        if (cyc > 0) mbar_wait(mb_empty + 8 * s, (cyc - 1) & 1);
        produce_stage(mb_full, sb, bid, u, s);
        if (++s == STAGES) { s = 0; cyc++; }
      }
    }
    return;
  }

  // ---------------- compute warps 0-7: 2(m) x 4(n), warp tile 64x32 ---------
  const int wr = wid >> 2;   // 0..1 (m)
  const int wc = wid & 3;    // 0..3 (n)
  const uint32_t a_lane_off = (wr * 4) * 512 + lane * 16;   // mfrag stride 512B
  const uint32_t b_lane_off = (wc * 2) * 512 + lane * 16;   // pair stride 512B

  int s = 0, cyc = 0;
  for (int ti = 0; ti < ntiles; ti++) {
    const int t = bid + GRID * ti;
    const int mt = t >> 5;
    const int nt = t & 31;

    float acc[4][4][4];
#pragma unroll
    for (int i = 0; i < 4; i++)
#pragma unroll
      for (int j = 0; j < 4; j++)
#pragma unroll
        for (int c = 0; c < 4; c++) acc[i][j][c] = 0.0f;

    for (int un = 0; un < UNITS_PER_TILE; un++) {
      mbar_wait(mb_full + 8 * s, cyc & 1);
      const uint32_t aB = sb + SMEM_HDR + s * STAGE_BYTES;
      const uint32_t bB = aB + A_STAGE_BYTES;

      uint32_t af[2][4][4], bf[2][2][4];
      // prefetch ks=0
#pragma unroll
      for (int mf = 0; mf < 4; mf++) LDS128(af[0][mf], aB + a_lane_off + mf * 512);
#pragma unroll
      for (int p = 0; p < 2; p++) LDS128(bf[0][p], bB + b_lane_off + p * 512);

#pragma unroll
      for (int ks = 0; ks < 8; ks++) {   // 8 K=16 steps across the 2 k-tiles
        const int cur = ks & 1, nxt = cur ^ 1;
        if (ks < 7) {
          const int kn = ks + 1;
          const uint32_t koff = (kn >> 2) * 16384 + (kn & 3) * 4096;
          const uint32_t a_addr = aB + koff + a_lane_off;
          const uint32_t b_addr = bB + koff + b_lane_off;
#pragma unroll
          for (int mf = 0; mf < 4; mf++) LDS128(af[nxt][mf], a_addr + mf * 512);
#pragma unroll
          for (int p = 0; p < 2; p++) LDS128(bf[nxt][p], b_addr + p * 512);
        }
#pragma unroll
        for (int mf = 0; mf < 4; mf++)
#pragma unroll
          for (int p = 0; p < 2; p++) {
            mma_f16(acc[mf][2 * p + 0], af[cur][mf], bf[cur][p][0], bf[cur][p][1]);
            mma_f16(acc[mf][2 * p + 1], af[cur][mf], bf[cur][p][2], bf[cur][p][3]);
          }
      }
      if (lane == 0) MBAR_ARRIVE(mb_empty + 8 * s);
      if (++s == STAGES) { s = 0; cyc++; }
    }

    // ---------------- epilogue: acc + bias -> out (overlaps producer) -------
    const int m_base = mt * BM + wr * 64 + (lane >> 2);
    const int n_base = nt * BN + wc * 32 + (lane & 3) * 2;
#pragma unroll
    for (int mf = 0; mf < 4; mf++) {
      const int m0 = m_base + mf * 16;
#pragma unroll
      for (int nf = 0; nf < 4; nf++) {
        const int n = n_base + nf * 8;
        const float2 bv = *reinterpret_cast<const float2*>(bias + n);
        float2 v0, v1;
        v0.x = acc[mf][nf][0] + bv.x;
        v0.y = acc[mf][nf][1] + bv.y;
        v1.x = acc[mf][nf][2] + bv.x;
        v1.y = acc[mf][nf][3] + bv.y;
        *reinterpret_cast<float2*>(out + (size_t)m0 * N_TOT + n) = v0;
        *reinterpret_cast<float2*>(out + (size_t)(m0 + 8) * N_TOT + n) = v1;
      }
    }
  }
}

// ===================== launch =====================
extern "C" void kernel_launch(void* const* d_in, const int* in_sizes, int n_in,
                              void* d_out, int out_size) {
  const float* x    = (const float*)d_in[0];   // [2,2048,4096] f32
  const int4*  q3   = (const int4*)d_in[1];    // [NUM_GROUPS*12] int32 byte values
  const float* norm = (const float*)d_in[2];   // [NUM_GROUPS] f32
  const float* bias = (const float*)d_in[3];   // [4096] f32
  float* out = (float*)d_out;                  // [2,2048,4096] f32

  prep_kernel<<<PREP_GRID, 256>>>(x, q3, norm);

  cudaFuncSetAttribute(gemm_kernel, cudaFuncAttributeMaxDynamicSharedMemorySize, SMEM_TOTAL);
  gemm_kernel<<<GRID, 288, SMEM_TOTAL>>>(bias, out);
}